// round 17
// baseline (speedup 1.0000x reference)
#include <cuda_runtime.h>
#include <cuda_bf16.h>
#include <cuda_fp16.h>

#define R_ROWS 4
#define NROWS  (R_ROWS + 2)

template<int N> struct IC { static constexpr int value = N; };

// silu via fast approx: v * rcp(1 + 2^(-v*log2e))
__device__ __forceinline__ float fast_silu(float v) {
    float e, r;
    asm("ex2.approx.f32 %0, %1;" : "=f"(e) : "f"(v * -1.442695041f));
    asm("rcp.approx.f32 %0, %1;" : "=f"(r) : "f"(1.0f + e));
    return v * r;
}

// Cubic coeffs of spline_f on cell j (j=11 -> all zero row):
// a0=(W0+4W1+W2)/6, a1=(W2-W0)/2, a2=(W0-2W1+W2)/2, a3=(W3-W0+3(W1-W2))/6
__device__ __forceinline__ void spline_coeffs(int j, int f,
                                              const float* __restrict__ sw,
                                              const float* __restrict__ ss,
                                              float a[4]) {
    a[0] = a[1] = a[2] = a[3] = 0.f;
    if (j < 11) {
        float scale = __ldg(&ss[f]);
        float W[4];
        #pragma unroll
        for (int c = 0; c < 4; c++) {
            int bi = j + c - 3;
            W[c] = (bi >= 0 && bi < 8) ? __ldg(&sw[f * 8 + bi]) * scale : 0.f;
        }
        const float S = 1.f / 6.f;
        a[0] = (W[0] + 4.f * W[1] + W[2]) * S;
        a[1] = (W[2] - W[0]) * 0.5f;
        a[2] = (W[0] - 2.f * W[1] + W[2]) * 0.5f;
        a[3] = (W[3] - W[0] + 3.f * (W[1] - W[2])) * S;
    }
}

// KAN 3x3 conv, shared KANLinear(9->1), cubic B-spline on uniform grid.
// R14 skeleton (warp-per-strip rolling, R=4, kh-trim, fp16 tables, half2
// pair Horner, 71-reg schedule) + send pair-packing on full-kh rows.
__global__ __launch_bounds__(128, 7)
void kan_conv_kernel(const float* __restrict__ x,
                     const float* __restrict__ bw,
                     const float* __restrict__ sw,
                     const float* __restrict__ ss,
                     float* __restrict__ out)
{
    __shared__ uint2 polyH[12 * 9];   // scalar table: [j][f] = {h2(a0,a1), h2(a2,a3)}
    __shared__ uint4 pairE[12 * 3];   // even px acc pair (lo=f3kh ->accO, hi=f3kh+1 ->accE)
    __shared__ uint4 pairO[12 * 3];   // odd  px acc pair (lo=f3kh+1->accO, hi=f3kh+2 ->accE)
    __shared__ uint4 sLp[12];         // send-left pair (f2 lo, f5 hi), spline only
    __shared__ uint4 sRp[12];         // send-right pair (f0 lo, f3 hi), spline only
    __shared__ float Zs[9];           // spline value at padding pixels (x=0)

    const int lane  = threadIdx.x & 31;
    const int warp  = threadIdx.x >> 5;
    const int img   = blockIdx.x >> 2;                  // 1024 blocks = 256 images x 4
    const int strip = ((blockIdx.x & 3) << 2) | warp;   // 0..15
    const int y0    = strip * R_ROWS;

    auto h2u = [](float a, float b) {
        __half2 h = __floats2half2_rn(a, b);
        return *reinterpret_cast<unsigned*>(&h);
    };

    // ---- scalar table + padding constants ----
    if (threadIdx.x < 108) {
        const int t = threadIdx.x;
        const int j = t / 9, f = t - j * 9;
        float a[4];
        spline_coeffs(j, f, sw, ss, a);
        polyH[t] = make_uint2(h2u(a[0], a[1]), h2u(a[2], a[3]));
        if (j == 5)   // x=0 -> cell 5, u=0.5, silu=0 (fp32 exact)
            Zs[f] = fmaf(fmaf(fmaf(a[3], 0.5f, a[2]), 0.5f, a[1]), 0.5f, a[0]);
    }
    // ---- packed acc-pair tables ----
    if (threadIdx.x < 72) {
        const int which = threadIdx.x / 36;        // 0 = even pair, 1 = odd pair
        const int e = threadIdx.x % 36;
        const int j = e / 3, kh = e - j * 3;
        const int flo = kh * 3 + which;
        float clo[4], chi[4];
        spline_coeffs(j, flo,     sw, ss, clo);
        spline_coeffs(j, flo + 1, sw, ss, chi);
        uint4 q;
        q.x = h2u(clo[0], chi[0]);
        q.y = h2u(clo[1], chi[1]);
        q.z = h2u(clo[2], chi[2]);
        q.w = h2u(clo[3], chi[3]);
        (which ? pairO : pairE)[j * 3 + kh] = q;
    }
    // ---- packed send-pair tables ----
    if (threadIdx.x >= 72 && threadIdx.x < 96) {
        const int t = threadIdx.x - 72;
        const int which = t / 12;                  // 0 = sL (f2,f5), 1 = sR (f0,f3)
        const int j = t % 12;
        const int flo = which ? 0 : 2;
        float clo[4], chi[4];
        spline_coeffs(j, flo,     sw, ss, clo);
        spline_coeffs(j, flo + 3, sw, ss, chi);
        uint4 q;
        q.x = h2u(clo[0], chi[0]);
        q.y = h2u(clo[1], chi[1]);
        q.z = h2u(clo[2], chi[2]);
        q.w = h2u(clo[3], chi[3]);
        (which ? sRp : sLp)[j] = q;
    }
    float bwr[9];
    #pragma unroll
    for (int f = 0; f < 9; f++) bwr[f] = __ldg(&bw[f]);
    __syncthreads();

    float Z[9];
    #pragma unroll
    for (int f = 0; f < 9; f++) Z[f] = Zs[f];

    const float* xcol = x   + img * 4096 + lane * 2;
    float*       ocol = out + img * 4096 + lane * 2;

    float accE[3] = {0.f, 0.f, 0.f};
    float accO[3] = {0.f, 0.f, 0.f};

    // scalar eval (fp16 coeffs, fp32 Horner, base folded)
    auto evalS = [&](int jbase, float u, float s, int f) {
        uint2 pk = polyH[jbase + f];
        float2 c01 = __half22float2(*reinterpret_cast<__half2*>(&pk.x));
        float2 c23 = __half22float2(*reinterpret_cast<__half2*>(&pk.y));
        float t = fmaf(c23.y, u, c23.x);
        t = fmaf(t, u, c01.y);
        t = fmaf(t, u, c01.x);
        return fmaf(s, bwr[f], t);
    };
    // half2 pair Horner (2 features at once)
    auto evalP = [](const uint4& q, __half2 u2) -> __half2 {
        __half2 t = __hfma2(*reinterpret_cast<const __half2*>(&q.w), u2,
                            *reinterpret_cast<const __half2*>(&q.z));
        t = __hfma2(t, u2, *reinterpret_cast<const __half2*>(&q.y));
        t = __hfma2(t, u2, *reinterpret_cast<const __half2*>(&q.x));
        return t;
    };

    auto row = [&](auto rc) {
        constexpr int r = rc.value;
        const int py = y0 - 1 + r;
        float2 p;
        if constexpr (r == 0 || r == NROWS - 1) {
            p = make_float2(0.f, 0.f);
            if (py >= 0 && py < 64) p = *(const float2*)(xcol + py * 64);
        } else {
            p = *(const float2*)(xcol + py * 64);
        }

        const float se = fast_silu(p.x);
        const float so = fast_silu(p.y);

        // cell locate; out-of-grid -> row 11 (all-zero coeffs)
        float xce = fmaf(p.x, 2.5f, 5.5f);          // (v+2.2)/0.4
        float jfe = floorf(xce);
        const float ue = xce - jfe;
        const int je = min((unsigned)(int)jfe, 11u);
        float xco = fmaf(p.y, 2.5f, 5.5f);
        float jfo = floorf(xco);
        const float uo = xco - jfo;
        const int jo = min((unsigned)(int)jfo, 11u);

        const __half2 u2e = __float2half2_rn(ue);
        const __half2 u2o = __float2half2_rn(uo);
        const int je3 = je * 3, jo3 = jo * 3;
        const int je9 = je * 9, jo9 = jo * 9;

        // out = py+1-kh in strip => kh in [r-3, r] ∩ [0,2]
        constexpr int kh_lo = (r > 3) ? (r - 3) : 0;
        constexpr int kh_hi = (r < 2) ? r : 2;

        // send evals: pair-packed on full-kh rows, scalar otherwise
        float sLv[3], sRv[3];
        if constexpr (kh_lo == 0 && kh_hi == 2) {
            float2 l01 = __half22float2(evalP(sLp[je], u2e));   // spline f2, f5
            sLv[0] = fmaf(se, bwr[2], l01.x);
            sLv[1] = fmaf(se, bwr[5], l01.y);
            sLv[2] = evalS(je9, ue, se, 8);
            float2 r01 = __half22float2(evalP(sRp[jo], u2o));   // spline f0, f3
            sRv[0] = fmaf(so, bwr[0], r01.x);
            sRv[1] = fmaf(so, bwr[3], r01.y);
            sRv[2] = evalS(jo9, uo, so, 6);
        } else {
            #pragma unroll
            for (int kh = kh_lo; kh <= kh_hi; kh++) {
                sLv[kh] = evalS(je9, ue, se, kh * 3 + 2);
                sRv[kh] = evalS(jo9, uo, so, kh * 3 + 0);
            }
        }

        #pragma unroll
        for (int kh = kh_lo; kh <= kh_hi; kh++) {
            __half2 spe = evalP(pairE[je3 + kh], u2e);
            __half2 spo = evalP(pairO[jo3 + kh], u2o);
            float2 sp = __half22float2(__hadd2(spe, spo));

            float aO = accO[2 - kh] + sp.x;          // spline (accO half)
            aO = fmaf(se, bwr[kh * 3 + 0], aO);      // even px base, kw0
            aO = fmaf(so, bwr[kh * 3 + 1], aO);      // odd  px base, kw1
            float aE = accE[2 - kh] + sp.y;          // spline (accE half)
            aE = fmaf(se, bwr[kh * 3 + 1], aE);      // even px base, kw1
            aE = fmaf(so, bwr[kh * 3 + 2], aE);      // odd  px base, kw2

            float rl = __shfl_down_sync(0xffffffffu, sLv[kh], 1);
            if (lane == 31) rl = Z[kh * 3 + 2];      // col 64 padding -> out col 63
            float rr = __shfl_up_sync(0xffffffffu, sRv[kh], 1);
            if (lane == 0)  rr = Z[kh * 3 + 0];      // col -1 padding -> out col 0

            accO[2 - kh] = aO + rl;
            accE[2 - kh] = aE + rr;
        }

        if constexpr (r >= 2) {
            *(float2*)(ocol + (y0 + r - 2) * 64) = make_float2(accE[0], accO[0]);
        }
        accE[0] = accE[1]; accE[1] = accE[2]; accE[2] = 0.f;
        accO[0] = accO[1]; accO[1] = accO[2]; accO[2] = 0.f;
    };

    row(IC<0>{}); row(IC<1>{}); row(IC<2>{});
    row(IC<3>{}); row(IC<4>{}); row(IC<5>{});
}

extern "C" void kernel_launch(void* const* d_in, const int* in_sizes, int n_in,
                              void* d_out, int out_size) {
    const float* x  = (const float*)d_in[0];  // (8,32,64,64)
    const float* bw = (const float*)d_in[1];  // (1,9)
    const float* sw = (const float*)d_in[2];  // (1,9,8)
    const float* ss = (const float*)d_in[3];  // (1,9)
    float* out = (float*)d_out;

    // 256 images x 16 strips, 4 warp-strips per block
    kan_conv_kernel<<<1024, 128>>>(x, bw, sw, ss, out);
}